// round 12
// baseline (speedup 1.0000x reference)
#include <cuda_runtime.h>
#include <cuda_bf16.h>
#include <cuda_fp16.h>
#include <math.h>
#include <stdint.h>

#define NN    50000
#define NE_MAX 1600000
#define IND   256
#define HID   128
#define BATCH_MAX 16384
#define BN_EPS 1e-5f

// ---------------- scratch ----------------
__device__ __align__(16) __half g_y16[(size_t)NN * 128];   // fp16 y; later reused as z1 (float, B x 128)
__device__ __align__(16) float  g_r[(size_t)NN * 128];
__device__ __align__(16) float  g_h[(size_t)NN * 128];     // h1 then h2 (fp32)
__device__ __align__(16) float  g_ep[(size_t)BATCH_MAX * 64];
__device__ int   g_cnt[NN];
__device__ int   g_cur[NN];
__device__ int   g_off[NN + 1];
__device__ int   g_csr[NE_MAX];
__device__ __align__(16) __nv_bfloat16 g_bth0[256 * 256];
__device__ __align__(16) __nv_bfloat16 g_btl0[256 * 256];
__device__ __align__(16) __nv_bfloat16 g_bth1[256 * 256];
__device__ __align__(16) __nv_bfloat16 g_btl1[256 * 256];

struct Aux {
    cudaStream_t s2;
    cudaEvent_t ev0, ev1;
    Aux() {
        cudaStreamCreateWithFlags(&s2, cudaStreamNonBlocking);
        cudaEventCreateWithFlags(&ev0, cudaEventDisableTiming);
        cudaEventCreateWithFlags(&ev1, cudaEventDisableTiming);
    }
};
static Aux g_aux;

__device__ __forceinline__ uint32_t smem_u32(const void* p) {
    uint32_t a;
    asm("{ .reg .u64 t; cvta.to.shared.u64 t, %1; cvt.u32.u64 %0, t; }" : "=r"(a) : "l"(p));
    return a;
}
__device__ __forceinline__ void ldm_x4(uint32_t& r0, uint32_t& r1, uint32_t& r2, uint32_t& r3, uint32_t addr) {
    asm volatile("ldmatrix.sync.aligned.m8n8.x4.shared.b16 {%0,%1,%2,%3}, [%4];"
                 : "=r"(r0), "=r"(r1), "=r"(r2), "=r"(r3) : "r"(addr));
}
__device__ __forceinline__ void mma16816(float* c, uint32_t a0, uint32_t a1, uint32_t a2, uint32_t a3,
                                         uint32_t b0, uint32_t b1) {
    asm volatile("mma.sync.aligned.m16n8k16.row.col.f32.bf16.bf16.f32 "
                 "{%0,%1,%2,%3}, {%4,%5,%6,%7}, {%8,%9}, {%0,%1,%2,%3};"
                 : "+f"(c[0]), "+f"(c[1]), "+f"(c[2]), "+f"(c[3])
                 : "r"(a0), "r"(a1), "r"(a2), "r"(a3), "r"(b0), "r"(b1));
}
__device__ __forceinline__ uint32_t packbf(__nv_bfloat16 a, __nv_bfloat16 b) {
    return ((uint32_t)__bfloat16_as_ushort(b) << 16) | __bfloat16_as_ushort(a);
}
__device__ __forceinline__ void cvt8(float4 a, float4 b, uint4& ph, uint4& pl) {
    __nv_bfloat16 h0 = __float2bfloat16(a.x), h1 = __float2bfloat16(a.y);
    __nv_bfloat16 h2 = __float2bfloat16(a.z), h3 = __float2bfloat16(a.w);
    __nv_bfloat16 h4 = __float2bfloat16(b.x), h5 = __float2bfloat16(b.y);
    __nv_bfloat16 h6 = __float2bfloat16(b.z), h7 = __float2bfloat16(b.w);
    __nv_bfloat16 l0 = __float2bfloat16(a.x - __bfloat162float(h0));
    __nv_bfloat16 l1 = __float2bfloat16(a.y - __bfloat162float(h1));
    __nv_bfloat16 l2 = __float2bfloat16(a.z - __bfloat162float(h2));
    __nv_bfloat16 l3 = __float2bfloat16(a.w - __bfloat162float(h3));
    __nv_bfloat16 l4 = __float2bfloat16(b.x - __bfloat162float(h4));
    __nv_bfloat16 l5 = __float2bfloat16(b.y - __bfloat162float(h5));
    __nv_bfloat16 l6 = __float2bfloat16(b.z - __bfloat162float(h6));
    __nv_bfloat16 l7 = __float2bfloat16(b.w - __bfloat162float(h7));
    ph = make_uint4(packbf(h0, h1), packbf(h2, h3), packbf(h4, h5), packbf(h6, h7));
    pl = make_uint4(packbf(l0, l1), packbf(l2, l3), packbf(l4, l5), packbf(l6, l7));
}
#define CP_ASYNC16(dst, src) asm volatile("cp.async.ca.shared.global [%0], [%1], 16;\n" :: "r"(dst), "l"(src))
#define CP_COMMIT()          asm volatile("cp.async.commit_group;\n" ::: "memory")
#define CP_WAIT0()           asm volatile("cp.async.wait_group 0;\n" ::: "memory")

// ================= CSR build =================
__global__ void count_k(const int* __restrict__ dst, int E)
{
    int i = blockIdx.x * blockDim.x + threadIdx.x;
    if (i < E) atomicAdd(&g_cnt[dst[i]], 1);
}
__global__ void scan_k(int n)
{
    __shared__ int part[1024];
    int tid = threadIdx.x;
    int chunk = (n + 1023) >> 10;
    int b = tid * chunk, e = min(b + chunk, n);
    int s = 0;
    for (int i = b; i < e; i++) s += g_cnt[i];
    part[tid] = s;
    __syncthreads();
    for (int o = 1; o < 1024; o <<= 1) {
        int v = (tid >= o) ? part[tid - o] : 0;
        __syncthreads();
        part[tid] += v;
        __syncthreads();
    }
    int run = tid ? part[tid - 1] : 0;
    for (int i = b; i < e; i++) { g_off[i] = run; g_cur[i] = run; run += g_cnt[i]; }
    if (tid == 0) g_off[n] = part[1023];
}
__global__ void fill_k(const int* __restrict__ src, const int* __restrict__ dst, int E)
{
    int i = blockIdx.x * blockDim.x + threadIdx.x;
    if (i < E) {
        int p = atomicAdd(&g_cur[dst[i]], 1);
        g_csr[p] = src[i];
    }
}

// ================= weight transpose + split =================
__global__ void conv_w(const float* __restrict__ wl, const float* __restrict__ wr, int K,
                       __nv_bfloat16* __restrict__ bh, __nv_bfloat16* __restrict__ bl)
{
    int idx = blockIdx.x * blockDim.x + threadIdx.x;
    if (idx >= 256 * K) return;
    int j = idx / K, k = idx - j * K;
    float v = (j < 128) ? wl[(size_t)k * 128 + j] : wr[(size_t)k * 128 + (j - 128)];
    __nv_bfloat16 h = __float2bfloat16(v);
    __nv_bfloat16 l = __float2bfloat16(v - __bfloat162float(h));
    bh[idx] = h;
    bl[idx] = l;
}

// ================= edge processor precompute =================
__global__ void ep_k(const float* __restrict__ ef, const float* __restrict__ epw,
                     const float* __restrict__ epb, int B)
{
    int i = blockIdx.x * blockDim.x + threadIdx.x;
    if (i >= B * 64) return;
    int row = i >> 6, j = i & 63;
    float v = __ldg(epb + j);
    #pragma unroll
    for (int k = 0; k < 6; k++) v = fmaf(__ldg(ef + row * 6 + k), __ldg(epw + k * 64 + j), v);
    g_ep[i] = fmaxf(v, 0.f);
}

// ================= bf16 split-2 GEMM, fused fp32->split A loader =================
// C halves: grid.y==0 -> y (fp16 g_y16), ==1 -> r (fp32 g_r).
// K-tile 32, segments {Ah*Bh, Ah*Bl, Al*Bh} run on resident tiles.
__global__ void __launch_bounds__(256, 2) gemm_mma(const float* __restrict__ A, int M, int K,
                                                   const __nv_bfloat16* __restrict__ Bh,
                                                   const __nv_bfloat16* __restrict__ Bl)
{
    __shared__ __align__(16) __nv_bfloat16 Ahs[2][128][40];
    __shared__ __align__(16) __nv_bfloat16 Als[2][128][40];
    __shared__ __align__(16) __nv_bfloat16 Bhs[2][128][40];
    __shared__ __align__(16) __nv_bfloat16 Bls[2][128][40];

    int tid = threadIdx.x, lane = tid & 31, warp = tid >> 5;
    int wr = warp & 3, wc = warp >> 2;
    int rm = blockIdx.x * 128;
    int bn0 = blockIdx.y * 128;

    // A loader mapping: row ar, col block ac (16 floats)
    int ar = tid >> 1, ac = (tid & 1) * 16;
    bool ga = (rm + ar) < M;
    const float* ap = A + (size_t)(ga ? rm + ar : 0) * K + ac;
    // B loader: row br, col block bc (16 bf16 per matrix via 2x cp.async)
    int br = tid >> 1, bc = (tid & 1) * 16;
    const __nv_bfloat16* bhp = Bh + (size_t)(bn0 + br) * K + bc;
    const __nv_bfloat16* blp = Bl + (size_t)(bn0 + br) * K + bc;
    uint32_t sBh0 = smem_u32(&Bhs[0][br][bc]), sBl0 = smem_u32(&Bls[0][br][bc]);
    uint32_t sBh1 = smem_u32(&Bhs[1][br][bc]), sBl1 = smem_u32(&Bls[1][br][bc]);

    int KT = K >> 5;

    // ---- preload tile 0 ----
    {
        float4 f0 = make_float4(0.f,0.f,0.f,0.f), f1 = f0, f2 = f0, f3 = f0;
        if (ga) { f0 = *(const float4*)(ap); f1 = *(const float4*)(ap + 4);
                  f2 = *(const float4*)(ap + 8); f3 = *(const float4*)(ap + 12); }
        uint4 ph, pl;
        cvt8(f0, f1, ph, pl);
        *(uint4*)&Ahs[0][ar][ac]     = ph; *(uint4*)&Als[0][ar][ac]     = pl;
        cvt8(f2, f3, ph, pl);
        *(uint4*)&Ahs[0][ar][ac + 8] = ph; *(uint4*)&Als[0][ar][ac + 8] = pl;
        CP_ASYNC16(sBh0,      bhp);
        CP_ASYNC16(sBh0 + 16, bhp + 8);
        CP_ASYNC16(sBl0,      blp);
        CP_ASYNC16(sBl0 + 16, blp + 8);
        CP_COMMIT();
        CP_WAIT0();
    }

    float acc[2][8][4];
    #pragma unroll
    for (int i = 0; i < 2; i++)
        #pragma unroll
        for (int j = 0; j < 8; j++)
            #pragma unroll
            for (int q = 0; q < 4; q++) acc[i][j][q] = 0.f;

    int arow = wr * 32 + (lane & 15);
    int acol8 = 8 * (lane >> 4);
    int brow = wc * 64 + (lane & 7) + 8 * (lane >> 4);
    int bcol8 = 8 * ((lane >> 3) & 1);

    for (int kt = 0; kt < KT; kt++) {
        __syncthreads();
        int cur = kt & 1, nb = cur ^ 1;
        float4 f0, f1, f2, f3;
        bool more = (kt + 1 < KT);
        if (more) {
            int k0 = (kt + 1) << 5;
            // B next via cp.async (no regs held)
            uint32_t dBh = (nb ? sBh1 : sBh0), dBl = (nb ? sBl1 : sBl0);
            CP_ASYNC16(dBh,      bhp + k0);
            CP_ASYNC16(dBh + 16, bhp + k0 + 8);
            CP_ASYNC16(dBl,      blp + k0);
            CP_ASYNC16(dBl + 16, blp + k0 + 8);
            CP_COMMIT();
            f0 = make_float4(0.f,0.f,0.f,0.f); f1 = f0; f2 = f0; f3 = f0;
            if (ga) { f0 = *(const float4*)(ap + k0); f1 = *(const float4*)(ap + k0 + 4);
                      f2 = *(const float4*)(ap + k0 + 8); f3 = *(const float4*)(ap + k0 + 12); }
        }

        // 3 segment passes on resident tiles
        #pragma unroll
        for (int sg = 0; sg < 3; sg++) {
            const __nv_bfloat16 (*As_)[40] = (sg < 2) ? Ahs[cur] : Als[cur];
            const __nv_bfloat16 (*Bs_)[40] = (sg == 1) ? Bls[cur] : Bhs[cur];
            #pragma unroll
            for (int kk = 0; kk < 2; kk++) {
                int kb = kk * 16;
                uint32_t a[2][4];
                #pragma unroll
                for (int mi = 0; mi < 2; mi++)
                    ldm_x4(a[mi][0], a[mi][1], a[mi][2], a[mi][3],
                           smem_u32(&As_[arow + mi * 16][kb + acol8]));
                uint32_t b[8][2];
                #pragma unroll
                for (int nj2 = 0; nj2 < 4; nj2++)
                    ldm_x4(b[nj2 * 2][0], b[nj2 * 2][1], b[nj2 * 2 + 1][0], b[nj2 * 2 + 1][1],
                           smem_u32(&Bs_[brow + nj2 * 16][kb + bcol8]));
                #pragma unroll
                for (int mi = 0; mi < 2; mi++)
                    #pragma unroll
                    for (int nj = 0; nj < 8; nj++)
                        mma16816(acc[mi][nj], a[mi][0], a[mi][1], a[mi][2], a[mi][3],
                                 b[nj][0], b[nj][1]);
            }
        }

        if (more) {
            uint4 ph, pl;
            cvt8(f0, f1, ph, pl);
            *(uint4*)&Ahs[nb][ar][ac]     = ph; *(uint4*)&Als[nb][ar][ac]     = pl;
            cvt8(f2, f3, ph, pl);
            *(uint4*)&Ahs[nb][ar][ac + 8] = ph; *(uint4*)&Als[nb][ar][ac + 8] = pl;
            CP_WAIT0();
        }
    }

    int col = wc * 64 + (lane & 3) * 2;
    if (blockIdx.y == 0) {
        #pragma unroll
        for (int mi = 0; mi < 2; mi++) {
            int r0g = rm + wr * 32 + mi * 16 + (lane >> 2);
            #pragma unroll
            for (int nj = 0; nj < 8; nj++) {
                if (r0g < M)
                    *(__half2*)(g_y16 + (size_t)r0g * 128 + col + nj * 8) =
                        __floats2half2_rn(acc[mi][nj][0], acc[mi][nj][1]);
                if (r0g + 8 < M)
                    *(__half2*)(g_y16 + (size_t)(r0g + 8) * 128 + col + nj * 8) =
                        __floats2half2_rn(acc[mi][nj][2], acc[mi][nj][3]);
            }
        }
    } else {
        #pragma unroll
        for (int mi = 0; mi < 2; mi++) {
            int r0g = rm + wr * 32 + mi * 16 + (lane >> 2);
            #pragma unroll
            for (int nj = 0; nj < 8; nj++) {
                if (r0g < M)
                    *(float2*)(g_r + (size_t)r0g * 128 + col + nj * 8) = make_float2(acc[mi][nj][0], acc[mi][nj][1]);
                if (r0g + 8 < M)
                    *(float2*)(g_r + (size_t)(r0g + 8) * 128 + col + nj * 8) = make_float2(acc[mi][nj][2], acc[mi][nj][3]);
            }
        }
    }
}

// ================= CSR gather (fp16 y), 2 edges/warp =================
#define ACCUM8(u) { \
    float2 f0 = __half22float2(*(__half2*)&(u).x); \
    float2 f1 = __half22float2(*(__half2*)&(u).y); \
    float2 f2 = __half22float2(*(__half2*)&(u).z); \
    float2 f3 = __half22float2(*(__half2*)&(u).w); \
    acc[0] += f0.x; acc[1] += f0.y; acc[2] += f1.x; acc[3] += f1.y; \
    acc[4] += f2.x; acc[5] += f2.y; acc[6] += f3.x; acc[7] += f3.y; }

__global__ void gather_k(const float* __restrict__ bias, int doRelu, int n)
{
    int node = (blockIdx.x * blockDim.x + threadIdx.x) >> 5;
    int lane = threadIdx.x & 31;
    if (node >= n) return;
    int s0 = g_off[node], s1 = g_off[node + 1];
    int grp = lane >> 4, ln = lane & 15;

    float acc[8];
    #pragma unroll
    for (int j = 0; j < 8; j++) acc[j] = 0.f;

    int e = s0 + grp;
    for (; e + 6 < s1; e += 8) {
        int i0 = g_csr[e], i1 = g_csr[e + 2], i2 = g_csr[e + 4], i3 = g_csr[e + 6];
        uint4 u0 = ((const uint4*)(g_y16 + (size_t)i0 * 128))[ln];
        uint4 u1 = ((const uint4*)(g_y16 + (size_t)i1 * 128))[ln];
        uint4 u2 = ((const uint4*)(g_y16 + (size_t)i2 * 128))[ln];
        uint4 u3 = ((const uint4*)(g_y16 + (size_t)i3 * 128))[ln];
        ACCUM8(u0); ACCUM8(u1); ACCUM8(u2); ACCUM8(u3);
    }
    for (; e < s1; e += 2) {
        int i0 = g_csr[e];
        uint4 u0 = ((const uint4*)(g_y16 + (size_t)i0 * 128))[ln];
        ACCUM8(u0);
    }
    #pragma unroll
    for (int j = 0; j < 8; j++) acc[j] += __shfl_xor_sync(0xffffffffu, acc[j], 16);

    if (grp == 0) {
        float dinv = 1.0f / fmaxf((float)(s1 - s0), 1.0f);
        float4 r0 = *(const float4*)(g_r + (size_t)node * 128 + ln * 8);
        float4 r1 = *(const float4*)(g_r + (size_t)node * 128 + ln * 8 + 4);
        float4 b0v = *(const float4*)(bias + ln * 8);
        float4 b1v = *(const float4*)(bias + ln * 8 + 4);
        float o[8];
        o[0] = fmaf(acc[0], dinv, b0v.x) + r0.x;
        o[1] = fmaf(acc[1], dinv, b0v.y) + r0.y;
        o[2] = fmaf(acc[2], dinv, b0v.z) + r0.z;
        o[3] = fmaf(acc[3], dinv, b0v.w) + r0.w;
        o[4] = fmaf(acc[4], dinv, b1v.x) + r1.x;
        o[5] = fmaf(acc[5], dinv, b1v.y) + r1.y;
        o[6] = fmaf(acc[6], dinv, b1v.z) + r1.z;
        o[7] = fmaf(acc[7], dinv, b1v.w) + r1.w;
        if (doRelu) {
            #pragma unroll
            for (int j = 0; j < 8; j++) o[j] = fmaxf(o[j], 0.f);
        }
        *(float4*)(g_h + (size_t)node * 128 + ln * 8)     = make_float4(o[0], o[1], o[2], o[3]);
        *(float4*)(g_h + (size_t)node * 128 + ln * 8 + 4) = make_float4(o[4], o[5], o[6], o[7]);
    }
}

// ================= predictor stage 1: persistent, 4 rows/warp =================
__global__ void pred1_k(const int* __restrict__ srcN, const int* __restrict__ tgtN,
                        const float* __restrict__ p1w, const float* __restrict__ p1b,
                        const float* __restrict__ gamma, const float* __restrict__ beta,
                        const float* __restrict__ mean, const float* __restrict__ var,
                        float* __restrict__ z1out, int B)
{
    extern __shared__ float sm[];
    float* w1s = sm;              // 40960
    float* b1s = w1s + 40960;     // 128
    float* scs = b1s + 128;       // 128
    float* shs = scs + 128;       // 128
    float* cws = shs + 128;       // 8 warps * 4 rows * 320 = 10240

    int tid = threadIdx.x;
    for (int i = tid; i < 10240; i += 256) ((float4*)w1s)[i] = ((const float4*)p1w)[i];
    if (tid < 128) {
        b1s[tid] = p1b[tid];
        float sc = gamma[tid] * rsqrtf(var[tid] + BN_EPS);
        scs[tid] = sc;
        shs[tid] = beta[tid] - mean[tid] * sc;
    }
    __syncthreads();

    int warp = tid >> 5, lane = tid & 31;
    float* cw = cws + warp * 1280;
    const float4* w14 = (const float4*)w1s;

    for (int base = (blockIdx.x * 8 + warp) * 4; base < B; base += gridDim.x * 32) {
        #pragma unroll
        for (int rr = 0; rr < 4; rr++) {
            int row = base + rr;
            int s = __ldg(srcN + row), t = __ldg(tgtN + row);
            ((float4*)(cw + rr * 320))[lane]      = ((const float4*)(g_h + (size_t)s * 128))[lane];
            ((float4*)(cw + rr * 320))[32 + lane] = ((const float4*)(g_h + (size_t)t * 128))[lane];
            ((float2*)(cw + rr * 320 + 256))[lane] = ((const float2*)(g_ep + (size_t)row * 64))[lane];
        }
        __syncwarp();

        float4 a[4];
        #pragma unroll
        for (int rr = 0; rr < 4; rr++) a[rr] = make_float4(0.f, 0.f, 0.f, 0.f);
        #pragma unroll 2
        for (int k = 0; k < 320; k++) {
            float4 w = w14[k * 32 + lane];
            #pragma unroll
            for (int rr = 0; rr < 4; rr++) {
                float c = cw[rr * 320 + k];
                a[rr].x = fmaf(c, w.x, a[rr].x);
                a[rr].y = fmaf(c, w.y, a[rr].y);
                a[rr].z = fmaf(c, w.z, a[rr].z);
                a[rr].w = fmaf(c, w.w, a[rr].w);
            }
        }
        float4 bb  = ((float4*)b1s)[lane];
        float4 sc4 = ((float4*)scs)[lane];
        float4 sh4 = ((float4*)shs)[lane];
        #pragma unroll
        for (int rr = 0; rr < 4; rr++) {
            float4 z;
            z.x = fmaf(fmaxf(a[rr].x + bb.x, 0.f), sc4.x, sh4.x);
            z.y = fmaf(fmaxf(a[rr].y + bb.y, 0.f), sc4.y, sh4.y);
            z.z = fmaf(fmaxf(a[rr].z + bb.z, 0.f), sc4.z, sh4.z);
            z.w = fmaf(fmaxf(a[rr].w + bb.w, 0.f), sc4.w, sh4.w);
            ((float4*)(z1out + (size_t)(base + rr) * 128))[lane] = z;
        }
        __syncwarp();
    }
}

// ================= predictor stages 2+3 =================
__global__ void pred2_k(const float* __restrict__ p2w, const float* __restrict__ p2b,
                        const float* __restrict__ p3w, const float* __restrict__ p3b,
                        const float* __restrict__ z1in, float* __restrict__ out, int B)
{
    __shared__ float w2s[8192];
    __shared__ float w3s[64], b2s[64];
    __shared__ float z1s[8][2][128];

    int tid = threadIdx.x;
    for (int i = tid; i < 2048; i += 256) ((float4*)w2s)[i] = ((const float4*)p2w)[i];
    if (tid < 64) { w3s[tid] = p3w[tid]; b2s[tid] = p2b[tid]; }
    __syncthreads();

    int warp = tid >> 5, lane = tid & 31;
    float b3 = __ldg(p3b);
    int pair = blockIdx.x * 8 + warp;
    int r0 = pair * 2, r1 = r0 + 1;
    if (r0 >= B) return;

    ((float4*)z1s[warp][0])[lane] = ((const float4*)(z1in + (size_t)r0 * 128))[lane];
    ((float4*)z1s[warp][1])[lane] = ((const float4*)(z1in + (size_t)r1 * 128))[lane];
    __syncwarp();

    float za0 = 0.f, zb0 = 0.f, za1 = 0.f, zb1 = 0.f;
    #pragma unroll 4
    for (int k = 0; k < 128; k++) {
        float wa = w2s[k * 64 + lane], wb = w2s[k * 64 + lane + 32];
        float q0 = z1s[warp][0][k], q1 = z1s[warp][1][k];
        za0 = fmaf(q0, wa, za0); zb0 = fmaf(q0, wb, zb0);
        za1 = fmaf(q1, wa, za1); zb1 = fmaf(q1, wb, zb1);
    }
    za0 = fmaxf(za0 + b2s[lane], 0.f);  zb0 = fmaxf(zb0 + b2s[lane + 32], 0.f);
    za1 = fmaxf(za1 + b2s[lane], 0.f);  zb1 = fmaxf(zb1 + b2s[lane + 32], 0.f);

    float p0 = fmaf(za0, w3s[lane], zb0 * w3s[lane + 32]);
    float p1 = fmaf(za1, w3s[lane], zb1 * w3s[lane + 32]);
    #pragma unroll
    for (int o = 16; o > 0; o >>= 1) {
        p0 += __shfl_down_sync(0xffffffffu, p0, o);
        p1 += __shfl_down_sync(0xffffffffu, p1, o);
    }
    if (lane == 0) {
        out[r0] = 1.f / (1.f + __expf(-(p0 + b3)));
        out[r1] = 1.f / (1.f + __expf(-(p1 + b3)));
    }
}

// ================= launch =================
extern "C" void kernel_launch(void* const* d_in, const int* in_sizes, int n_in,
                              void* d_out, int out_size)
{
    const float* x     = (const float*)d_in[0];
    const int*   eidx  = (const int*)d_in[1];
    const int*   srcN  = (const int*)d_in[2];
    const int*   tgtN  = (const int*)d_in[3];
    const float* ef    = (const float*)d_in[4];
    const float* wl0   = (const float*)d_in[5];
    const float* b0    = (const float*)d_in[6];
    const float* wr0   = (const float*)d_in[7];
    const float* wl1   = (const float*)d_in[8];
    const float* b1    = (const float*)d_in[9];
    const float* wr1   = (const float*)d_in[10];
    const float* epw   = (const float*)d_in[11];
    const float* epb   = (const float*)d_in[12];
    const float* p1w   = (const float*)d_in[13];
    const float* p1b   = (const float*)d_in[14];
    const float* gma   = (const float*)d_in[15];
    const float* bta   = (const float*)d_in[16];
    const float* bmean = (const float*)d_in[17];
    const float* bvar  = (const float*)d_in[18];
    const float* p2w   = (const float*)d_in[19];
    const float* p2b   = (const float*)d_in[20];
    const float* p3w   = (const float*)d_in[21];
    const float* p3b   = (const float*)d_in[22];
    float* out = (float*)d_out;

    int N = in_sizes[0] / IND;     // 50000
    int E = in_sizes[1] / 2;       // 1600000
    int B = in_sizes[2];           // 16384
    const int* esrc = eidx;
    const int* edst = eidx + E;

    void *cntp = nullptr, *z1p = nullptr, *hp = nullptr;
    void *bth0 = nullptr, *btl0 = nullptr, *bth1 = nullptr, *btl1 = nullptr;
    cudaGetSymbolAddress(&cntp, g_cnt);
    cudaGetSymbolAddress(&z1p,  g_y16);   // reuse as float z1 buffer
    cudaGetSymbolAddress(&hp,   g_h);
    cudaGetSymbolAddress(&bth0, g_bth0);
    cudaGetSymbolAddress(&btl0, g_btl0);
    cudaGetSymbolAddress(&bth1, g_bth1);
    cudaGetSymbolAddress(&btl1, g_btl1);

    // ---- aux stream: layer-1 weights, edge-proc, CSR build ----
    cudaEventRecord(g_aux.ev0, 0);
    cudaStreamWaitEvent(g_aux.s2, g_aux.ev0, 0);
    conv_w<<<(256 * HID + 255) / 256, 256, 0, g_aux.s2>>>(wl1, wr1, HID,
        (__nv_bfloat16*)bth1, (__nv_bfloat16*)btl1);
    ep_k<<<(B * 64 + 255) / 256, 256, 0, g_aux.s2>>>(ef, epw, epb, B);
    cudaMemsetAsync(cntp, 0, (size_t)N * sizeof(int), g_aux.s2);
    int egrid = (E + 255) / 256;
    count_k<<<egrid, 256, 0, g_aux.s2>>>(edst, E);
    scan_k<<<1, 1024, 0, g_aux.s2>>>(N);
    fill_k<<<egrid, 256, 0, g_aux.s2>>>(esrc, edst, E);
    cudaEventRecord(g_aux.ev1, g_aux.s2);

    int ngrid = (N * 32 + 255) / 256;
    dim3 ggrid((N + 127) / 128, 2);

    // ---- Layer 0 (default stream) ----
    conv_w<<<(256 * IND + 255) / 256, 256>>>(wl0, wr0, IND,
        (__nv_bfloat16*)bth0, (__nv_bfloat16*)btl0);
    gemm_mma<<<ggrid, 256>>>(x, N, IND, (const __nv_bfloat16*)bth0, (const __nv_bfloat16*)btl0);
    cudaStreamWaitEvent(0, g_aux.ev1, 0);
    gather_k<<<ngrid, 256>>>(b0, 1, N);   // h1 = relu(...), fp32 in g_h

    // ---- Layer 1 ----
    gemm_mma<<<ggrid, 256>>>((const float*)hp, N, HID, (const __nv_bfloat16*)bth1, (const __nv_bfloat16*)btl1);
    gather_k<<<ngrid, 256>>>(b1, 0, N);   // h2, fp32 in g_h

    // ---- Predictor ----
    size_t sm1 = (size_t)(40960 + 128 + 128 + 128 + 10240) * sizeof(float);
    cudaFuncSetAttribute(pred1_k, cudaFuncAttributeMaxDynamicSharedMemorySize, (int)sm1);
    pred1_k<<<148, 256, sm1>>>(srcN, tgtN, p1w, p1b, gma, bta, bmean, bvar, (float*)z1p, B);
    pred2_k<<<(B + 15) / 16, 256>>>(p2w, p2b, p3w, p3b, (const float*)z1p, out, B);
}